// round 9
// baseline (speedup 1.0000x reference)
#include <cuda_runtime.h>
#include <math.h>

typedef unsigned long long u64;

#define BL    800
#define NIT   8192
#define NROW  8992

#define OFF_CATGY 0
#define OFF_DSC   128000
#define OFF_DCAND 134400
#define OFF_EMB   1182976
#define OFF_ECAND 1285376
#define OFF_LOSS  2333952

__device__ float g_wf  [128 * 128];
__device__ float g_bf  [128];
__device__ float g_agg [128 * 128];
__device__ float g_pd  [128 * 128];
__device__ float g_pdT [128 * 128];
__device__ float g_pk  [BL * 128];
__device__ float g_pkc [NIT * 128];

union F4U { float4 f; u64 u[2]; float s[4]; };

__device__ __forceinline__ u64 pack2(float lo, float hi) {
    u64 r; asm("mov.b64 %0, {%1,%2};" : "=l"(r) : "f"(lo), "f"(hi)); return r;
}
__device__ __forceinline__ void unpack2(u64 v, float& lo, float& hi) {
    asm("mov.b64 {%0,%1}, %2;" : "=f"(lo), "=f"(hi) : "l"(v));
}
__device__ __forceinline__ u64 fma2(u64 a, u64 b, u64 c) {
    u64 r; asm("fma.rn.f32x2 %0, %1, %2, %3;" : "=l"(r) : "l"(a), "l"(b), "l"(c)); return r;
}
__device__ __forceinline__ u64 add2(u64 a, u64 b) {
    u64 r; asm("add.rn.f32x2 %0, %1, %2;" : "=l"(r) : "l"(a), "l"(b)); return r;
}
__device__ __forceinline__ u64 relu2(u64 v) {
    float a, b; unpack2(v, a, b);
    a = fmaxf(a, 0.f); b = fmaxf(b, 0.f);
    return pack2(a, b);
}

// 8x4 micro over 128x64 tile. As: [128][132] floats (k-major rows, 128 rows).
// Bs: [128][68] floats (k-major cols, 64 cols). rows ty*8, cols tx*4.
#define MICRO84(AS, BS)                                                       \
    u64 acc[8][2];                                                            \
    _Pragma("unroll")                                                         \
    for (int i = 0; i < 8; i++) { acc[i][0] = 0ull; acc[i][1] = 0ull; }       \
    _Pragma("unroll 4")                                                       \
    for (int k = 0; k < 128; k++) {                                           \
        F4U a0; a0.f = *(const float4*)&(AS)[k * 132 + ty * 8];               \
        F4U a1; a1.f = *(const float4*)&(AS)[k * 132 + ty * 8 + 4];           \
        F4U q;  q.f  = *(const float4*)&(BS)[k * 68 + tx * 4];                \
        _Pragma("unroll")                                                     \
        for (int i = 0; i < 4; i++) {                                         \
            u64 ad = pack2(a0.s[i], a0.s[i]);                                 \
            acc[i][0] = fma2(ad, q.u[0], acc[i][0]);                          \
            acc[i][1] = fma2(ad, q.u[1], acc[i][1]);                          \
        }                                                                     \
        _Pragma("unroll")                                                     \
        for (int i = 0; i < 4; i++) {                                         \
            u64 ad = pack2(a1.s[i], a1.s[i]);                                 \
            acc[4 + i][0] = fma2(ad, q.u[0], acc[4 + i][0]);                  \
            acc[4 + i][1] = fma2(ad, q.u[1], acc[4 + i][1]);                  \
        }                                                                     \
    }

// 4x8 micro over 64x128 tile. As: [128][68] (64 rows). Bs: [128][132] (128 cols).
#define MICRO48(AS, BS)                                                       \
    u64 acc[4][4];                                                            \
    _Pragma("unroll")                                                         \
    for (int i = 0; i < 4; i++)                                               \
        _Pragma("unroll")                                                     \
        for (int j = 0; j < 4; j++) acc[i][j] = 0ull;                         \
    _Pragma("unroll 4")                                                       \
    for (int k = 0; k < 128; k++) {                                           \
        F4U a;  a.f  = *(const float4*)&(AS)[k * 68 + ty * 4];                \
        F4U q0; q0.f = *(const float4*)&(BS)[k * 132 + tx * 8];               \
        F4U q1; q1.f = *(const float4*)&(BS)[k * 132 + tx * 8 + 4];           \
        _Pragma("unroll")                                                     \
        for (int i = 0; i < 4; i++) {                                         \
            u64 ad = pack2(a.s[i], a.s[i]);                                   \
            acc[i][0] = fma2(ad, q0.u[0], acc[i][0]);                         \
            acc[i][1] = fma2(ad, q0.u[1], acc[i][1]);                         \
            acc[i][2] = fma2(ad, q1.u[0], acc[i][2]);                         \
            acc[i][3] = fma2(ad, q1.u[1], acc[i][3]);                         \
        }                                                                     \
    }

// ===========================================================================
// K1: blocks 0..127 : fused emb@Wd + logsumexp (64 l x 128 cols, 4x8 micro)
//     blocks 128..129: wf = Wk@Wk1 (128x64 tiles, 8x4 micro)
//     block  130     : bf = bk@Wk1
// ===========================================================================
__global__ void __launch_bounds__(256, 2)
k1_lse_fold(const int* __restrict__ inp,
            const float* __restrict__ table,
            const float* __restrict__ Wd,
            const float* __restrict__ Wk,
            const float* __restrict__ Wk1,
            const float* __restrict__ bk,
            float* __restrict__ agg,
            float* __restrict__ wf, float* __restrict__ bf) {
    __shared__ __align__(16) char sb[102400];
    int bx = blockIdx.x, tid = threadIdx.x;
    int tx = tid & 15, ty = tid >> 4;

    if (bx < 128) {
        float* As  = (float*)sb;               // [128][68]  (l rows)
        float* Bs  = (float*)(sb + 34816);     // [128][132] (128 cols)
        float* red = As;                       // reuse after main loop
        int b = bx >> 3, cb = bx & 7;          // 8 slabs x 128 cols
        const float4* t4 = (const float4*)table;
#pragma unroll
        for (int p = 0; p < 8; p++) {
            int i = tid + p * 256;               // 2048 = 64 l x 32 k4
            int l = i & 63, k4 = i >> 6;
            float4 v = make_float4(0.f, 0.f, 0.f, 0.f);
            if (l < 50) { int idx = inp[b * 50 + l]; v = t4[idx * 32 + k4]; }
            As[(k4 * 4 + 0) * 68 + l] = v.x;
            As[(k4 * 4 + 1) * 68 + l] = v.y;
            As[(k4 * 4 + 2) * 68 + l] = v.z;
            As[(k4 * 4 + 3) * 68 + l] = v.w;
        }
#pragma unroll
        for (int p = 0; p < 16; p++) {
            int i = tid + p * 256;               // 4096 = 128 k x 32 c4
            int k = i >> 5, c4 = (i & 31) * 4;
            *(float4*)&Bs[k * 132 + c4] = *(const float4*)(Wd + k * 1024 + cb * 128 + c4);
        }
        __syncthreads();

        MICRO48(As, Bs);

        float vals[4][8];
#pragma unroll
        for (int i = 0; i < 4; i++)
#pragma unroll
            for (int j = 0; j < 4; j++)
                unpack2(acc[i][j], vals[i][j * 2], vals[i][j * 2 + 1]);
        int nval = 50 - ty * 4; if (nval > 4) nval = 4; if (nval < 0) nval = 0;

        __syncthreads();
#pragma unroll
        for (int u = 0; u < 8; u++) {
            float mm = -INFINITY;
            for (int i = 0; i < nval; i++) mm = fmaxf(mm, vals[i][u]);
            red[ty * 132 + tx * 8 + u] = mm;
        }
        __syncthreads();
        float M[8];
#pragma unroll
        for (int u = 0; u < 8; u++) {
            float mm = -INFINITY;
#pragma unroll
            for (int t = 0; t < 16; t++) mm = fmaxf(mm, red[t * 132 + tx * 8 + u]);
            M[u] = mm;
        }
        __syncthreads();
#pragma unroll
        for (int u = 0; u < 8; u++) {
            float s = 0.f;
            for (int i = 0; i < nval; i++) s += __expf(vals[i][u] - M[u]);
            red[ty * 132 + tx * 8 + u] = s;
        }
        __syncthreads();
        if (ty == 0) {
#pragma unroll
            for (int u = 0; u < 8; u++) {
                float S = 0.f;
#pragma unroll
                for (int t = 0; t < 16; t++) S += red[t * 132 + tx * 8 + u];
                agg[b * 1024 + cb * 128 + tx * 8 + u] = M[u] + __logf(S);
            }
        }
    } else if (bx < 130) {
        float* As = (float*)sb;                // [128][132] (128 Wk rows)
        float* Bs = (float*)(sb + 67584);      // [128][68]  (64 cols)
        int bn = (bx - 128) * 64;
#pragma unroll
        for (int p = 0; p < 16; p++) {
            int i = tid + p * 256;               // 4096 = 128 rows x 32 k4
            int r = i & 127, k4 = i >> 7;
            float4 v = *(const float4*)(Wk + r * 128 + k4 * 4);
            As[(k4 * 4 + 0) * 132 + r] = v.x;
            As[(k4 * 4 + 1) * 132 + r] = v.y;
            As[(k4 * 4 + 2) * 132 + r] = v.z;
            As[(k4 * 4 + 3) * 132 + r] = v.w;
        }
#pragma unroll
        for (int p = 0; p < 8; p++) {
            int i = tid + p * 256;               // 2048 = 128 k x 16 c4
            int k = i >> 4, c4 = (i & 15) * 4;
            *(float4*)&Bs[k * 68 + c4] = *(const float4*)(Wk1 + k * 128 + bn + c4);
        }
        __syncthreads();

        MICRO84(As, Bs);

#pragma unroll
        for (int i = 0; i < 8; i++) {
            F4U o; o.u[0] = acc[i][0]; o.u[1] = acc[i][1];
            *(float4*)(wf + (ty * 8 + i) * 128 + bn + tx * 4) = o.f;
        }
    } else {
        if (tid < 128) {
            float acc = 0.f;
#pragma unroll 8
            for (int h = 0; h < 128; h++)
                acc = fmaf(__ldg(bk + h), __ldg(Wk1 + h * 128 + tid), acc);
            bf[tid] = acc;
        }
    }
}

// ===========================================================================
// K2: blocks 0..141  : pk/pkc GEMM (128 rows x 64 cols, 8x4) + gather + emb out
//     blocks 142..157: catgy (128 x 64 tiles)
//     blocks 158..159: pd (128 x 64 tiles, +pdT)
//     block  160     : demand_sim_loss
// ===========================================================================
__global__ void __launch_bounds__(256, 2)
k2_gemm_heads(const int* __restrict__ inp, const int* __restrict__ cand,
              const float* __restrict__ table,
              const float* __restrict__ wf, const float* __restrict__ bf,
              const float* __restrict__ agg,
              const float* __restrict__ Wc, const float* __restrict__ bc,
              const float* __restrict__ W1, const float* __restrict__ b1,
              float* __restrict__ out,
              float* __restrict__ pk, float* __restrict__ pkc,
              float* __restrict__ pd, float* __restrict__ pdT) {
    __shared__ __align__(16) char sb[102400];
    float* As = (float*)sb;                // [128][132]
    float* Bs = (float*)(sb + 67584);      // [128][68]
    int bx = blockIdx.x, tid = threadIdx.x;
    int tx = tid & 15, ty = tid >> 4;

    if (bx < 142) {
        int rb = bx >> 1, cs = bx & 1;
        int bm = rb * 128, bn = cs * 64;
        const float4* t4 = (const float4*)table;
#pragma unroll
        for (int p = 0; p < 16; p++) {
            int i = tid + p * 256;               // 4096 = 128 rows x 32 k4
            int r = i & 127, k4 = i >> 7;
            int row = bm + r;
            float4 v = make_float4(0.f, 0.f, 0.f, 0.f);
            if (row < NROW) {
                int idx = (row < BL) ? inp[row] : cand[row - BL];
                v = t4[idx * 32 + k4];
                if (cs == 0) {
                    float* dst = (row < BL) ? (out + OFF_EMB + row * 128)
                                            : (out + OFF_ECAND + (row - BL) * 128);
                    ((float4*)dst)[k4] = v;
                }
            }
            As[(k4 * 4 + 0) * 132 + r] = v.x;
            As[(k4 * 4 + 1) * 132 + r] = v.y;
            As[(k4 * 4 + 2) * 132 + r] = v.z;
            As[(k4 * 4 + 3) * 132 + r] = v.w;
        }
#pragma unroll
        for (int p = 0; p < 8; p++) {
            int i = tid + p * 256;               // 2048 = 128 k x 16 c4
            int k = i >> 4, c4 = (i & 15) * 4;
            *(float4*)&Bs[k * 68 + c4] = *(const float4*)(wf + k * 128 + bn + c4);
        }
        __syncthreads();

        MICRO84(As, Bs);

        float4 bv = *(const float4*)(bf + bn + tx * 4);
#pragma unroll
        for (int i = 0; i < 8; i++) {
            int row = bm + ty * 8 + i;
            if (row >= NROW) continue;
            F4U o; o.u[0] = acc[i][0]; o.u[1] = acc[i][1];
            o.s[0] += bv.x; o.s[1] += bv.y; o.s[2] += bv.z; o.s[3] += bv.w;
            float* dst = (row < BL) ? (pk + row * 128) : (pkc + (row - BL) * 128);
            *(float4*)(dst + bn + tx * 4) = o.f;
        }
    } else if (bx < 160) {
        const float* B; const float* bias; float* C; float* CT; int N, bn;
        if (bx < 158) { int t = bx - 142; B = Wc; bias = bc; C = out + OFF_CATGY;
                        CT = nullptr; N = 1000; bn = t * 64; }
        else          { int t = bx - 158; B = W1; bias = b1; C = pd; CT = pdT;
                        N = 128; bn = t * 64; }

#pragma unroll
        for (int p = 0; p < 16; p++) {
            int i = tid + p * 256;               // 4096 = 128 rows x 32 k4
            int r = i & 127, k4 = i >> 7;
            float4 v = *(const float4*)(agg + r * 128 + k4 * 4);
            As[(k4 * 4 + 0) * 132 + r] = v.x;
            As[(k4 * 4 + 1) * 132 + r] = v.y;
            As[(k4 * 4 + 2) * 132 + r] = v.z;
            As[(k4 * 4 + 3) * 132 + r] = v.w;
        }
#pragma unroll
        for (int p = 0; p < 8; p++) {
            int i = tid + p * 256;
            int k = i >> 4, c4 = (i & 15) * 4;
            int c = bn + c4;
            float4 v = make_float4(0.f, 0.f, 0.f, 0.f);
            const float* brow = B + k * N;
            if (c + 3 < N) v = *(const float4*)(brow + c);
            else {
                if (c     < N) v.x = brow[c];
                if (c + 1 < N) v.y = brow[c + 1];
                if (c + 2 < N) v.z = brow[c + 2];
            }
            *(float4*)&Bs[k * 68 + c4] = v;
        }
        __syncthreads();

        MICRO84(As, Bs);

        int c0 = bn + tx * 4;
        float bv[4];
#pragma unroll
        for (int u = 0; u < 4; u++) bv[u] = (c0 + u < N) ? bias[c0 + u] : 0.f;
#pragma unroll
        for (int i = 0; i < 8; i++) {
            int r = ty * 8 + i;
            F4U o; o.u[0] = acc[i][0]; o.u[1] = acc[i][1];
            o.s[0] += bv[0]; o.s[1] += bv[1]; o.s[2] += bv[2]; o.s[3] += bv[3];
            if (c0 + 3 < N) *(float4*)(C + r * N + c0) = o.f;
            else {
#pragma unroll
                for (int u = 0; u < 4; u++)
                    if (c0 + u < N) C[r * N + c0 + u] = o.s[u];
            }
            if (CT) {
#pragma unroll
                for (int u = 0; u < 4; u++) CT[(c0 + u) * 128 + r] = o.s[u];
            }
        }
    } else {
        float* inv  = (float*)sb;
        float* redl = (float*)sb + 128;
        if (tid < 128) {
            const float* a = agg + tid * 128;
            float s = 0.f;
#pragma unroll 8
            for (int h = 0; h < 128; h++) s = fmaf(a[h], a[h], s);
            inv[tid] = 1.f / (sqrtf(s) + 1e-12f);
        }
        __syncthreads();
        if (tid < 128) {
            float accv = 0.f;
            for (int b = 0; b < 16; b++) {
                float sv = 0.f, sq = 0.f;
#pragma unroll
                for (int d = 0; d < 8; d++) {
                    float x = agg[(b * 8 + d) * 128 + tid] * inv[b * 8 + d];
                    sv += x; sq = fmaf(x, x, sq);
                }
                accv += sv * sv - sq;
            }
            redl[tid] = accv;
        }
        __syncthreads();
        if (tid == 0) {
            float t = 0.f;
            for (int i = 0; i < 128; i++) t += redl[i];
            out[OFF_LOSS] = t / 896.f;
        }
    }
}

// ===========================================================================
// K3 (R6 version, unchanged): blocks 0..255 cand relu-GEMM (64x64);
//     blocks 256..275 dscore
// ===========================================================================
__global__ void __launch_bounds__(256, 3)
k3_scores(const float* __restrict__ pdT, const float* __restrict__ pd,
          const float* __restrict__ pkc, const float* __restrict__ pk,
          const float* __restrict__ w,
          float* __restrict__ out) {
    __shared__ __align__(16) char sb[70656];
    int bx = blockIdx.x, tid = threadIdx.x;

    if (bx < 256) {
        float* Ps  = (float*)sb;               // [128][68] k-major bd
        float* Qs  = (float*)(sb + 34816);     // [128][68] k-major items
        u64*   ws2 = (u64*)(sb + 69632);       // [128]
        int bdb = (bx >> 7) * 64, itb = (bx & 127) * 64;
        int tx = tid & 15, ty = tid >> 4;

#pragma unroll
        for (int p = 0; p < 8; p++) {
            int i = tid + p * 256;
            int k = i >> 4, r4 = (i & 15) * 4;
            *(float4*)&Ps[k * 68 + r4] = *(const float4*)(pdT + k * 128 + bdb + r4);
        }
#pragma unroll
        for (int p = 0; p < 8; p++) {
            int i = tid + p * 256;
            int itl = i & 63, k4 = i >> 6;
            float4 v = *(const float4*)(pkc + (itb + itl) * 128 + k4 * 4);
            Qs[(k4 * 4 + 0) * 68 + itl] = v.x;
            Qs[(k4 * 4 + 1) * 68 + itl] = v.y;
            Qs[(k4 * 4 + 2) * 68 + itl] = v.z;
            Qs[(k4 * 4 + 3) * 68 + itl] = v.w;
        }
        if (tid < 128) { float wv = w[tid]; ws2[tid] = pack2(wv, wv); }
        __syncthreads();

        u64 acc[4][2];
#pragma unroll
        for (int i = 0; i < 4; i++) { acc[i][0] = 0ull; acc[i][1] = 0ull; }

#pragma unroll 4
        for (int k = 0; k < 128; k++) {
            F4U a4; a4.f = *(const float4*)&Ps[k * 68 + ty * 4];
            F4U q;  q.f  = *(const float4*)&Qs[k * 68 + tx * 4];
            u64 w2 = ws2[k];
#pragma unroll
            for (int i = 0; i < 4; i++) {
                u64 ad = pack2(a4.s[i], a4.s[i]);
                acc[i][0] = fma2(relu2(add2(ad, q.u[0])), w2, acc[i][0]);
                acc[i][1] = fma2(relu2(add2(ad, q.u[1])), w2, acc[i][1]);
            }
        }

#pragma unroll
        for (int i = 0; i < 4; i++) {
            int row = bdb + ty * 4 + i;
            F4U o; o.u[0] = acc[i][0]; o.u[1] = acc[i][1];
            *(float4*)(out + OFF_DCAND + (size_t)row * NIT + itb + tx * 4) = o.f;
        }
    } else {
        int wid0 = (bx - 256) * 8 + (tid >> 5);   // 0..159
        int lane = tid & 31;
        const float4* w4 = (const float4*)w;
        float4 ww = w4[lane];
#pragma unroll
        for (int rep = 0; rep < 5; rep++) {
            int wid = wid0 + rep * 160;
            if (wid >= 800) break;
            int b = wid / 50, l = wid % 50;
            const float4* k4 = (const float4*)(pk + (b * 50 + l) * 128);
            float4 c = k4[lane];
#pragma unroll
            for (int d = 0; d < 8; d++) {
                const float4* p4 = (const float4*)(pd + (b * 8 + d) * 128);
                float4 a = p4[lane];
                float acc = fmaxf(a.x + c.x, 0.f) * ww.x
                          + fmaxf(a.y + c.y, 0.f) * ww.y
                          + fmaxf(a.z + c.z, 0.f) * ww.z
                          + fmaxf(a.w + c.w, 0.f) * ww.w;
#pragma unroll
                for (int o = 16; o > 0; o >>= 1) acc += __shfl_down_sync(0xffffffffu, acc, o);
                if (lane == 0) out[OFF_DSC + b * 400 + l * 8 + d] = acc;
            }
        }
    }
}

// ===========================================================================
extern "C" void kernel_launch(void* const* d_in, const int* in_sizes, int n_in,
                              void* d_out, int out_size) {
    const int*   input = (const int*)d_in[0];
    const int*   cand  = (const int*)d_in[1];
    const float* table = (const float*)d_in[4];
    const float* Wd    = (const float*)d_in[5];
    const float* Wk    = (const float*)d_in[6];
    const float* bk    = (const float*)d_in[7];
    const float* W1    = (const float*)d_in[8];
    const float* b1    = (const float*)d_in[9];
    const float* wsc   = (const float*)d_in[10];
    const float* Wc    = (const float*)d_in[11];
    const float* bc    = (const float*)d_in[12];
    float* out = (float*)d_out;

    float *wf, *bf, *agg, *pd, *pdT, *pk, *pkc;
    cudaGetSymbolAddress((void**)&wf,  g_wf);
    cudaGetSymbolAddress((void**)&bf,  g_bf);
    cudaGetSymbolAddress((void**)&agg, g_agg);
    cudaGetSymbolAddress((void**)&pd,  g_pd);
    cudaGetSymbolAddress((void**)&pdT, g_pdT);
    cudaGetSymbolAddress((void**)&pk,  g_pk);
    cudaGetSymbolAddress((void**)&pkc, g_pkc);

    const float* Wk1 = W1 + 128 * 128;

    k1_lse_fold  <<<131, 256>>>(input, table, Wd, Wk, Wk1, bk, agg, wf, bf);
    k2_gemm_heads<<<161, 256>>>(input, cand, table, wf, bf, agg,
                                Wc, bc, W1, b1, out, pk, pkc, pd, pdT);
    k3_scores    <<<276, 256>>>(pdT, pd, pkc, pk, wsc, out);
}

// round 11
// speedup vs baseline: 1.0848x; 1.0848x over previous
#include <cuda_runtime.h>
#include <math.h>

typedef unsigned long long u64;

#define BL    800
#define NIT   8192
#define NROW  8992

#define OFF_CATGY 0
#define OFF_DSC   128000
#define OFF_DCAND 134400
#define OFF_EMB   1182976
#define OFF_ECAND 1285376
#define OFF_LOSS  2333952

__device__ float g_wf  [128 * 128];
__device__ float g_bf  [128];
__device__ float g_agg [128 * 128];
__device__ float g_pd  [128 * 128];
__device__ float g_pdT [128 * 128];
__device__ float g_pk  [BL * 128];
__device__ float g_pkc [NIT * 128];

union F4U { float4 f; u64 u[2]; float s[4]; };

__device__ __forceinline__ u64 pack2(float lo, float hi) {
    u64 r; asm("mov.b64 %0, {%1,%2};" : "=l"(r) : "f"(lo), "f"(hi)); return r;
}
__device__ __forceinline__ void unpack2(u64 v, float& lo, float& hi) {
    asm("mov.b64 {%0,%1}, %2;" : "=f"(lo), "=f"(hi) : "l"(v));
}
__device__ __forceinline__ u64 fma2(u64 a, u64 b, u64 c) {
    u64 r; asm("fma.rn.f32x2 %0, %1, %2, %3;" : "=l"(r) : "l"(a), "l"(b), "l"(c)); return r;
}
__device__ __forceinline__ u64 add2(u64 a, u64 b) {
    u64 r; asm("add.rn.f32x2 %0, %1, %2;" : "=l"(r) : "l"(a), "l"(b)); return r;
}
__device__ __forceinline__ u64 relu2(u64 v) {
    float a, b; unpack2(v, a, b);
    a = fmaxf(a, 0.f); b = fmaxf(b, 0.f);
    return pack2(a, b);
}

// 4x4 micro-tile over 64x64 block tile. As/Bs: [128][68] floats k-major.
// rows ty*4 (ty=tid>>4), cols tx*4 (tx=tid&15).
#define MICRO44(AS, BS)                                                       \
    u64 acc[4][2];                                                            \
    _Pragma("unroll")                                                         \
    for (int i = 0; i < 4; i++) { acc[i][0] = 0ull; acc[i][1] = 0ull; }       \
    _Pragma("unroll 4")                                                       \
    for (int k = 0; k < 128; k++) {                                           \
        F4U a4; a4.f = *(const float4*)&(AS)[k * 68 + ty * 4];                \
        F4U q;  q.f  = *(const float4*)&(BS)[k * 68 + tx * 4];                \
        _Pragma("unroll")                                                     \
        for (int i = 0; i < 4; i++) {                                         \
            u64 ad = pack2(a4.s[i], a4.s[i]);                                 \
            acc[i][0] = fma2(ad, q.u[0], acc[i][0]);                          \
            acc[i][1] = fma2(ad, q.u[1], acc[i][1]);                          \
        }                                                                     \
    }

// ===========================================================================
// K1: blocks 0..255 : fused emb@Wd + logsumexp (64 l x 64 cols per block)
//     blocks 256..259: wf = Wk@Wk1 (64x64 tiles)
//     block  260     : bf = bk@Wk1
// ===========================================================================
__global__ void __launch_bounds__(256, 3)
k1_lse_fold(const int* __restrict__ inp,
            const float* __restrict__ table,
            const float* __restrict__ Wd,
            const float* __restrict__ Wk,
            const float* __restrict__ Wk1,
            const float* __restrict__ bk,
            float* __restrict__ agg,
            float* __restrict__ wf, float* __restrict__ bf) {
    __shared__ __align__(16) char sb[69632];
    float* As = (float*)sb;                // [128][68]
    float* Bs = (float*)(sb + 34816);      // [128][68]
    float* red = As;                       // reuse after main loop
    int bx = blockIdx.x, tid = threadIdx.x;
    int tx = tid & 15, ty = tid >> 4;

    if (bx < 256) {
        int b = bx >> 4, cb = bx & 15;     // 16 slabs x 64 cols
        const float4* t4 = (const float4*)table;
#pragma unroll
        for (int p = 0; p < 8; p++) {
            int i = tid + p * 256;               // 2048 = 64 l x 32 k4
            int l = i & 63, k4 = i >> 6;
            float4 v = make_float4(0.f, 0.f, 0.f, 0.f);
            if (l < 50) { int idx = inp[b * 50 + l]; v = t4[idx * 32 + k4]; }
            As[(k4 * 4 + 0) * 68 + l] = v.x;
            As[(k4 * 4 + 1) * 68 + l] = v.y;
            As[(k4 * 4 + 2) * 68 + l] = v.z;
            As[(k4 * 4 + 3) * 68 + l] = v.w;
        }
#pragma unroll
        for (int p = 0; p < 8; p++) {
            int i = tid + p * 256;               // 2048 = 128 k x 16 c4
            int k = i >> 4, c4 = (i & 15) * 4;
            *(float4*)&Bs[k * 68 + c4] = *(const float4*)(Wd + k * 1024 + cb * 64 + c4);
        }
        __syncthreads();

        MICRO44(As, Bs);

        float vals[4][4];
#pragma unroll
        for (int i = 0; i < 4; i++) {
            unpack2(acc[i][0], vals[i][0], vals[i][1]);
            unpack2(acc[i][1], vals[i][2], vals[i][3]);
        }
        int nval = 50 - ty * 4; if (nval > 4) nval = 4; if (nval < 0) nval = 0;

        __syncthreads();
#pragma unroll
        for (int u = 0; u < 4; u++) {
            float mm = -INFINITY;
            for (int i = 0; i < nval; i++) mm = fmaxf(mm, vals[i][u]);
            red[ty * 68 + tx * 4 + u] = mm;
        }
        __syncthreads();
        float M[4];
#pragma unroll
        for (int u = 0; u < 4; u++) {
            float mm = -INFINITY;
#pragma unroll
            for (int t = 0; t < 16; t++) mm = fmaxf(mm, red[t * 68 + tx * 4 + u]);
            M[u] = mm;
        }
        __syncthreads();
#pragma unroll
        for (int u = 0; u < 4; u++) {
            float s = 0.f;
            for (int i = 0; i < nval; i++) s += __expf(vals[i][u] - M[u]);
            red[ty * 68 + tx * 4 + u] = s;
        }
        __syncthreads();
        if (ty == 0) {
#pragma unroll
            for (int u = 0; u < 4; u++) {
                float S = 0.f;
#pragma unroll
                for (int t = 0; t < 16; t++) S += red[t * 68 + tx * 4 + u];
                agg[b * 1024 + cb * 64 + tx * 4 + u] = M[u] + __logf(S);
            }
        }
    } else if (bx < 260) {
        int t = bx - 256;
        int bm = (t >> 1) * 64, bn = (t & 1) * 64;
#pragma unroll
        for (int p = 0; p < 8; p++) {
            int i = tid + p * 256;               // 64 r x 32 k4
            int r = i & 63, k4 = i >> 6;
            float4 v = *(const float4*)(Wk + (bm + r) * 128 + k4 * 4);
            As[(k4 * 4 + 0) * 68 + r] = v.x;
            As[(k4 * 4 + 1) * 68 + r] = v.y;
            As[(k4 * 4 + 2) * 68 + r] = v.z;
            As[(k4 * 4 + 3) * 68 + r] = v.w;
        }
#pragma unroll
        for (int p = 0; p < 8; p++) {
            int i = tid + p * 256;
            int k = i >> 4, c4 = (i & 15) * 4;
            *(float4*)&Bs[k * 68 + c4] = *(const float4*)(Wk1 + k * 128 + bn + c4);
        }
        __syncthreads();

        MICRO44(As, Bs);

#pragma unroll
        for (int i = 0; i < 4; i++) {
            F4U o; o.u[0] = acc[i][0]; o.u[1] = acc[i][1];
            *(float4*)(wf + (bm + ty * 4 + i) * 128 + bn + tx * 4) = o.f;
        }
    } else {
        if (tid < 128) {
            float acc = 0.f;
#pragma unroll 8
            for (int h = 0; h < 128; h++)
                acc = fmaf(__ldg(bk + h), __ldg(Wk1 + h * 128 + tid), acc);
            bf[tid] = acc;
        }
    }
}

// ===========================================================================
// K2: blocks 0..281  : pk/pkc GEMM (64 rows x 64 cols) + gather + emb out
//     blocks 282..313: catgy 64x64 tiles
//     blocks 314..317: pd 64x64 tiles (+pdT)
//     block  318     : demand_sim_loss
// ===========================================================================
__global__ void __launch_bounds__(256, 3)
k2_gemm_heads(const int* __restrict__ inp, const int* __restrict__ cand,
              const float* __restrict__ table,
              const float* __restrict__ wf, const float* __restrict__ bf,
              const float* __restrict__ agg,
              const float* __restrict__ Wc, const float* __restrict__ bc,
              const float* __restrict__ W1, const float* __restrict__ b1,
              float* __restrict__ out,
              float* __restrict__ pk, float* __restrict__ pkc,
              float* __restrict__ pd, float* __restrict__ pdT) {
    __shared__ __align__(16) char sb[69632];
    float* As = (float*)sb;                // [128][68]
    float* Bs = (float*)(sb + 34816);      // [128][68]
    int bx = blockIdx.x, tid = threadIdx.x;
    int tx = tid & 15, ty = tid >> 4;

    if (bx < 282) {
        int rb = bx >> 1, cs = bx & 1;
        int bm = rb * 64, bn = cs * 64;
        const float4* t4 = (const float4*)table;
#pragma unroll
        for (int p = 0; p < 8; p++) {
            int i = tid + p * 256;
            int r = i & 63, k4 = i >> 6;
            int row = bm + r;
            float4 v = make_float4(0.f, 0.f, 0.f, 0.f);
            if (row < NROW) {
                int idx = (row < BL) ? inp[row] : cand[row - BL];
                v = t4[idx * 32 + k4];
                if (cs == 0) {
                    float* dst = (row < BL) ? (out + OFF_EMB + row * 128)
                                            : (out + OFF_ECAND + (row - BL) * 128);
                    ((float4*)dst)[k4] = v;
                }
            }
            As[(k4 * 4 + 0) * 68 + r] = v.x;
            As[(k4 * 4 + 1) * 68 + r] = v.y;
            As[(k4 * 4 + 2) * 68 + r] = v.z;
            As[(k4 * 4 + 3) * 68 + r] = v.w;
        }
#pragma unroll
        for (int p = 0; p < 8; p++) {
            int i = tid + p * 256;
            int k = i >> 4, c4 = (i & 15) * 4;
            *(float4*)&Bs[k * 68 + c4] = *(const float4*)(wf + k * 128 + bn + c4);
        }
        __syncthreads();

        MICRO44(As, Bs);

        float4 bv = *(const float4*)(bf + bn + tx * 4);
#pragma unroll
        for (int i = 0; i < 4; i++) {
            int row = bm + ty * 4 + i;
            if (row >= NROW) continue;
            F4U o; o.u[0] = acc[i][0]; o.u[1] = acc[i][1];
            o.s[0] += bv.x; o.s[1] += bv.y; o.s[2] += bv.z; o.s[3] += bv.w;
            float* dst = (row < BL) ? (pk + row * 128) : (pkc + (row - BL) * 128);
            *(float4*)(dst + bn + tx * 4) = o.f;
        }
    } else if (bx < 318) {
        const float* B; const float* bias; float* C; float* CT; int N, bm, bn;
        if (bx < 314) { int t = bx - 282; B = Wc; bias = bc; C = out + OFF_CATGY;
                        CT = nullptr; N = 1000; bm = (t >> 4) * 64; bn = (t & 15) * 64; }
        else          { int t = bx - 314; B = W1; bias = b1; C = pd; CT = pdT;
                        N = 128; bm = (t >> 1) * 64; bn = (t & 1) * 64; }

#pragma unroll
        for (int p = 0; p < 8; p++) {
            int i = tid + p * 256;
            int r = i & 63, k4 = i >> 6;
            float4 v = *(const float4*)(agg + (bm + r) * 128 + k4 * 4);
            As[(k4 * 4 + 0) * 68 + r] = v.x;
            As[(k4 * 4 + 1) * 68 + r] = v.y;
            As[(k4 * 4 + 2) * 68 + r] = v.z;
            As[(k4 * 4 + 3) * 68 + r] = v.w;
        }
#pragma unroll
        for (int p = 0; p < 8; p++) {
            int i = tid + p * 256;
            int k = i >> 4, c4 = (i & 15) * 4;
            int c = bn + c4;
            float4 v = make_float4(0.f, 0.f, 0.f, 0.f);
            const float* brow = B + k * N;
            if (c + 3 < N) v = *(const float4*)(brow + c);
            else {
                if (c     < N) v.x = brow[c];
                if (c + 1 < N) v.y = brow[c + 1];
                if (c + 2 < N) v.z = brow[c + 2];
            }
            *(float4*)&Bs[k * 68 + c4] = v;
        }
        __syncthreads();

        MICRO44(As, Bs);

        int c0 = bn + tx * 4;
        float bv[4];
#pragma unroll
        for (int u = 0; u < 4; u++) bv[u] = (c0 + u < N) ? bias[c0 + u] : 0.f;
#pragma unroll
        for (int i = 0; i < 4; i++) {
            int r = bm + ty * 4 + i;
            F4U o; o.u[0] = acc[i][0]; o.u[1] = acc[i][1];
            o.s[0] += bv[0]; o.s[1] += bv[1]; o.s[2] += bv[2]; o.s[3] += bv[3];
            if (c0 + 3 < N) *(float4*)(C + r * N + c0) = o.f;
            else {
#pragma unroll
                for (int u = 0; u < 4; u++)
                    if (c0 + u < N) C[r * N + c0 + u] = o.s[u];
            }
            if (CT) {
#pragma unroll
                for (int u = 0; u < 4; u++) CT[(c0 + u) * 128 + r] = o.s[u];
            }
        }
    } else {
        float* inv  = (float*)sb;
        float* redl = (float*)sb + 128;
        if (tid < 128) {
            const float* a = agg + tid * 128;
            float s = 0.f;
#pragma unroll 8
            for (int h = 0; h < 128; h++) s = fmaf(a[h], a[h], s);
            inv[tid] = 1.f / (sqrtf(s) + 1e-12f);
        }
        __syncthreads();
        if (tid < 128) {
            float accv = 0.f;
            for (int b = 0; b < 16; b++) {
                float sv = 0.f, sq = 0.f;
#pragma unroll
                for (int d = 0; d < 8; d++) {
                    float x = agg[(b * 8 + d) * 128 + tid] * inv[b * 8 + d];
                    sv += x; sq = fmaf(x, x, sq);
                }
                accv += sv * sv - sq;
            }
            redl[tid] = accv;
        }
        __syncthreads();
        if (tid == 0) {
            float t = 0.f;
            for (int i = 0; i < 128; i++) t += redl[i];
            out[OFF_LOSS] = t / 896.f;
        }
    }
}

// ===========================================================================
// K3: blocks 0..255 : cand relu-GEMM (64 bd x 64 items)
//     blocks 256..275: dscore (160 warps x 5 reps)
// ===========================================================================
__global__ void __launch_bounds__(256, 3)
k3_scores(const float* __restrict__ pdT, const float* __restrict__ pd,
          const float* __restrict__ pkc, const float* __restrict__ pk,
          const float* __restrict__ w,
          float* __restrict__ out) {
    __shared__ __align__(16) char sb[70656];
    int bx = blockIdx.x, tid = threadIdx.x;

    if (bx < 256) {
        float* Ps  = (float*)sb;               // [128][68] k-major bd
        float* Qs  = (float*)(sb + 34816);     // [128][68] k-major items
        u64*   ws2 = (u64*)(sb + 69632);       // [128]
        int bdb = (bx >> 7) * 64, itb = (bx & 127) * 64;
        int tx = tid & 15, ty = tid >> 4;

#pragma unroll
        for (int p = 0; p < 8; p++) {
            int i = tid + p * 256;             // 2048 = 128 k x 16 r4
            int k = i >> 4, r4 = (i & 15) * 4;
            *(float4*)&Ps[k * 68 + r4] = *(const float4*)(pdT + k * 128 + bdb + r4);
        }
#pragma unroll
        for (int p = 0; p < 8; p++) {
            int i = tid + p * 256;             // 2048 = 64 it x 32 k4
            int itl = i & 63, k4 = i >> 6;
            float4 v = *(const float4*)(pkc + (itb + itl) * 128 + k4 * 4);
            Qs[(k4 * 4 + 0) * 68 + itl] = v.x;
            Qs[(k4 * 4 + 1) * 68 + itl] = v.y;
            Qs[(k4 * 4 + 2) * 68 + itl] = v.z;
            Qs[(k4 * 4 + 3) * 68 + itl] = v.w;
        }
        if (tid < 128) { float wv = w[tid]; ws2[tid] = pack2(wv, wv); }
        __syncthreads();

        u64 acc[4][2];
#pragma unroll
        for (int i = 0; i < 4; i++) { acc[i][0] = 0ull; acc[i][1] = 0ull; }

#pragma unroll 4
        for (int k = 0; k < 128; k++) {
            F4U a4; a4.f = *(const float4*)&Ps[k * 68 + ty * 4];
            F4U q;  q.f  = *(const float4*)&Qs[k * 68 + tx * 4];
            u64 w2 = ws2[k];
#pragma unroll
            for (int i = 0; i < 4; i++) {
                u64 ad = pack2(a4.s[i], a4.s[i]);
                acc[i][0] = fma2(relu2(add2(ad, q.u[0])), w2, acc[i][0]);
                acc[i][1] = fma2(relu2(add2(ad, q.u[1])), w2, acc[i][1]);
            }
        }

#pragma unroll
        for (int i = 0; i < 4; i++) {
            int row = bdb + ty * 4 + i;
            F4U o; o.u[0] = acc[i][0]; o.u[1] = acc[i][1];
            *(float4*)(out + OFF_DCAND + (size_t)row * NIT + itb + tx * 4) = o.f;
        }
    } else {
        int wid0 = (bx - 256) * 8 + (tid >> 5);   // 0..159
        int lane = tid & 31;
        const float4* w4 = (const float4*)w;
        float4 ww = w4[lane];
#pragma unroll
        for (int rep = 0; rep < 5; rep++) {
            int wid = wid0 + rep * 160;
            if (wid >= 800) break;
            int b = wid / 50, l = wid % 50;
            const float4* k4 = (const float4*)(pk + (b * 50 + l) * 128);
            float4 c = k4[lane];
#pragma unroll
            for (int d = 0; d < 8; d++) {
                const float4* p4 = (const float4*)(pd + (b * 8 + d) * 128);
                float4 a = p4[lane];
                float acc = fmaxf(a.x + c.x, 0.f) * ww.x
                          + fmaxf(a.y + c.y, 0.f) * ww.y
                          + fmaxf(a.z + c.z, 0.f) * ww.z
                          + fmaxf(a.w + c.w, 0.f) * ww.w;
#pragma unroll
                for (int o = 16; o > 0; o >>= 1) acc += __shfl_down_sync(0xffffffffu, acc, o);
                if (lane == 0) out[OFF_DSC + b * 400 + l * 8 + d] = acc;
            }
        }
    }
}

// ===========================================================================
extern "C" void kernel_launch(void* const* d_in, const int* in_sizes, int n_in,
                              void* d_out, int out_size) {
    const int*   input = (const int*)d_in[0];
    const int*   cand  = (const int*)d_in[1];
    const float* table = (const float*)d_in[4];
    const float* Wd    = (const float*)d_in[5];
    const float* Wk    = (const float*)d_in[6];
    const float* bk    = (const float*)d_in[7];
    const float* W1    = (const float*)d_in[8];
    const float* b1    = (const float*)d_in[9];
    const float* wsc   = (const float*)d_in[10];
    const float* Wc    = (const float*)d_in[11];
    const float* bc    = (const float*)d_in[12];
    float* out = (float*)d_out;

    float *wf, *bf, *agg, *pd, *pdT, *pk, *pkc;
    cudaGetSymbolAddress((void**)&wf,  g_wf);
    cudaGetSymbolAddress((void**)&bf,  g_bf);
    cudaGetSymbolAddress((void**)&agg, g_agg);
    cudaGetSymbolAddress((void**)&pd,  g_pd);
    cudaGetSymbolAddress((void**)&pdT, g_pdT);
    cudaGetSymbolAddress((void**)&pk,  g_pk);
    cudaGetSymbolAddress((void**)&pkc, g_pkc);

    const float* Wk1 = W1 + 128 * 128;

    k1_lse_fold  <<<261, 256>>>(input, table, Wd, Wk, Wk1, bk, agg, wf, bf);
    k2_gemm_heads<<<319, 256>>>(input, cand, table, wf, bf, agg,
                                Wc, bc, W1, b1, out, pk, pkc, pd, pdT);
    k3_scores    <<<276, 256>>>(pdT, pd, pkc, pk, wsc, out);
}